// round 10
// baseline (speedup 1.0000x reference)
#include <cuda_runtime.h>
#include <cstdint>

// Problem constants
#define B_    10      // 2 * IMG_COUNT sequences
#define T_    576     // tokens per sequence
#define C_    1280    // channels
#define H_    20      // heads
#define HD_   64      // head dim
#define P_    5       // plates
#define NSEL_ 288     // selected tokens per plate
#define TK_   1728    // kv length
#define BQ_   64
#define BKV_  64
#define NCH_  (TK_/BKV_)   // 27

// Scratch (device globals: allocation APIs are forbidden)
__device__ __align__(256) float g_Q [B_*T_*C_];
__device__ __align__(256) float g_K [B_*T_*C_];
__device__ __align__(256) float g_V [B_*T_*C_];
__device__ __align__(256) float g_AO[B_*T_*C_];
__device__ int g_kvrows[B_*TK_];

// ---------------------------------------------------------------------------
// Portable tf32 tensor-core MMA (sm_80+). HW reads operand bits[31:13] (RZ
// truncation) -- exploited for the big/small 3xTF32 split.
// ---------------------------------------------------------------------------
__device__ __forceinline__ void mma_tf32(float* c, const uint32_t* a, const uint32_t* b) {
    asm volatile(
        "mma.sync.aligned.m16n8k8.row.col.f32.tf32.tf32.f32 "
        "{%0,%1,%2,%3}, {%4,%5,%6,%7}, {%8,%9}, {%0,%1,%2,%3};"
        : "+f"(c[0]), "+f"(c[1]), "+f"(c[2]), "+f"(c[3])
        : "r"(a[0]), "r"(a[1]), "r"(a[2]), "r"(a[3]), "r"(b[0]), "r"(b[1]));
}

__device__ __forceinline__ uint32_t tf32_small(float v) {
    uint32_t big = __float_as_uint(v) & 0xFFFFE000u;
    return __float_as_uint(v - __uint_as_float(big));
}

__device__ __forceinline__ uint32_t smem_u32(const void* p) {
    uint32_t a;
    asm("{ .reg .u64 t; cvta.to.shared.u64 t, %1; cvt.u32.u64 %0, t; }" : "=r"(a) : "l"(p));
    return a;
}

#define CP_ASYNC16(smem, gptr) \
    asm volatile("cp.async.cg.shared.global [%0], [%1], 16;" :: "r"(smem), "l"(gptr))
#define CP_COMMIT()  asm volatile("cp.async.commit_group;" ::: "memory")
#define CP_WAIT(n)   asm volatile("cp.async.wait_group %0;" :: "n"(n) : "memory")

// ---------------------------------------------------------------------------
// Build per-(s,i) KV row index table (int64/int32 runtime detect).
// ---------------------------------------------------------------------------
__global__ void build_kv_kernel(const void* __restrict__ idx_raw) {
    const int*       i32 = (const int*)idx_raw;
    const long long* i64 = (const long long*)idx_raw;
    bool is64 = true;
    #pragma unroll 8
    for (int k = 0; k < 64; k++) {
        if (i32[2*k + 1] != 0) { is64 = false; break; }
    }
    const int b = blockIdx.x;
    const int s = b / P_, i = b % P_;
    for (int m = threadIdx.x; m < TK_; m += blockDim.x) {
        int row;
        if (m < (P_-1)*NSEL_) {
            int prel = m / NSEL_;
            int p    = prel + (prel >= i ? 1 : 0);
            int j    = m - prel * NSEL_;
            int tok  = is64 ? (int)i64[p*NSEL_ + j] : i32[p*NSEL_ + j];
            row = (s*P_ + p) * T_ + tok;
        } else {
            row = (s*P_ + i) * T_ + (m - (P_-1)*NSEL_);
        }
        g_kvrows[b*TK_ + m] = row;
    }
}

// ---------------------------------------------------------------------------
// 3xTF32 GEMM core (128x128 tile, 8 warps, BK=32). Shared by QKV and O.
// (unchanged from passing R8)
// ---------------------------------------------------------------------------
__device__ __forceinline__ void gemm_tile_body(
    const float* __restrict__ A, const float* __restrict__ Bw,
    const float* __restrict__ bias, float* __restrict__ Y,
    int N, int K, int m0, int n0)
{
    __shared__ float As[128][36];
    __shared__ float Bs[128][36];

    const int tid = threadIdx.x, wid = tid >> 5, lane = tid & 31;
    const int g = lane >> 2, tig = lane & 3;
    const int wm = (wid & 1) * 64, wn = (wid >> 1) * 32;
    const int NST = K >> 5;

    const int r = tid >> 1, half = tid & 1;
    const float* pA = A  + (size_t)(m0 + r) * K + half * 16;
    const float* pB = Bw + (size_t)(n0 + r) * K + half * 16;

    float acc[16][4];
    #pragma unroll
    for (int t = 0; t < 16; t++)
        #pragma unroll
        for (int v = 0; v < 4; v++) acc[t][v] = 0.f;

    float4 ra[4], rb[4];
    #pragma unroll
    for (int j = 0; j < 4; j++) {
        ra[j] = *(const float4*)(pA + j*4);
        rb[j] = *(const float4*)(pB + j*4);
    }

    for (int s = 0; s < NST; s++) {
        #pragma unroll
        for (int j = 0; j < 4; j++) {
            *(float4*)&As[r][half*16 + j*4] = ra[j];
            *(float4*)&Bs[r][half*16 + j*4] = rb[j];
        }
        __syncthreads();

        if (s + 1 < NST) {
            const float* a2 = pA + (s+1) * 32;
            const float* b2 = pB + (s+1) * 32;
            #pragma unroll
            for (int j = 0; j < 4; j++) {
                ra[j] = *(const float4*)(a2 + j*4);
                rb[j] = *(const float4*)(b2 + j*4);
            }
        }

        #pragma unroll
        for (int kb = 0; kb < 32; kb += 8) {
            uint32_t af[4][4], asm_[4][4], bf[4][2], bsm[4][2];
            #pragma unroll
            for (int mt = 0; mt < 4; mt++) {
                const int rb0 = wm + mt*16 + g;
                float v0 = As[rb0    ][kb + tig    ];
                float v1 = As[rb0 + 8][kb + tig    ];
                float v2 = As[rb0    ][kb + tig + 4];
                float v3 = As[rb0 + 8][kb + tig + 4];
                af[mt][0] = __float_as_uint(v0); asm_[mt][0] = tf32_small(v0);
                af[mt][1] = __float_as_uint(v1); asm_[mt][1] = tf32_small(v1);
                af[mt][2] = __float_as_uint(v2); asm_[mt][2] = tf32_small(v2);
                af[mt][3] = __float_as_uint(v3); asm_[mt][3] = tf32_small(v3);
            }
            #pragma unroll
            for (int nt = 0; nt < 4; nt++) {
                const int nb0 = wn + nt*8 + g;
                float w0 = Bs[nb0][kb + tig    ];
                float w1 = Bs[nb0][kb + tig + 4];
                bf[nt][0] = __float_as_uint(w0); bsm[nt][0] = tf32_small(w0);
                bf[nt][1] = __float_as_uint(w1); bsm[nt][1] = tf32_small(w1);
            }
            #pragma unroll
            for (int mt = 0; mt < 4; mt++)
                #pragma unroll
                for (int nt = 0; nt < 4; nt++) {
                    float* c = acc[mt*4 + nt];
                    mma_tf32(c, af[mt],   bf[nt]);
                    mma_tf32(c, af[mt],   bsm[nt]);
                    mma_tf32(c, asm_[mt], bf[nt]);
                }
        }
        __syncthreads();
    }

    #pragma unroll
    for (int mt = 0; mt < 4; mt++) {
        #pragma unroll
        for (int nt = 0; nt < 4; nt++) {
            const float* c = acc[mt*4 + nt];
            const int row = m0 + wm + mt*16 + g;
            const int col = n0 + wn + nt*8 + 2*tig;
            float b0c = 0.f, b1c = 0.f;
            if (bias) { b0c = bias[col]; b1c = bias[col + 1]; }
            float2 v0 = make_float2(c[0] + b0c, c[1] + b1c);
            float2 v1 = make_float2(c[2] + b0c, c[3] + b1c);
            *(float2*)(Y + (size_t)row       * N + col) = v0;
            *(float2*)(Y + (size_t)(row + 8) * N + col) = v1;
        }
    }
}

// Fused Q/K/V projection: blockIdx.z selects weight + destination.
__global__ __launch_bounds__(256) void gemm_qkv_kernel(
    const float* __restrict__ hs,
    const float* __restrict__ Wq, const float* __restrict__ Wk,
    const float* __restrict__ Wv,
    float* __restrict__ Qp, float* __restrict__ Kp, float* __restrict__ Vp)
{
    const int z = blockIdx.z;
    const float* Bw = (z == 0) ? Wq : (z == 1) ? Wk : Wv;
    float*       Y  = (z == 0) ? Qp : (z == 1) ? Kp : Vp;
    gemm_tile_body(hs, Bw, nullptr, Y, C_, C_, blockIdx.y * 128, blockIdx.x * 128);
}

// Output projection (with bias).
__global__ __launch_bounds__(256) void gemm_o_kernel(
    const float* __restrict__ A, const float* __restrict__ Wo,
    const float* __restrict__ bo, float* __restrict__ Y)
{
    gemm_tile_body(A, Wo, bo, Y, C_, C_, blockIdx.y * 128, blockIdx.x * 128);
}

// ---------------------------------------------------------------------------
// Tensor-core flash attention (3xTF32), BKV=64 chunks, cp.async double-buffer.
// 27 chunks (vs 54): halves sync rounds, softmax rounds, pacc rescales.
// Dynamic smem (floats):
//   Qs[64][68] | Ks[2][64][68] | Vs[2][64][72] | Ss[64][68] | rowscale | rowinv
// = 107,008 B per CTA -> 2 CTAs/SM.
// S phase: warp(mt=w&3, nhs=w>>2) owns S[mt*16..+16][nhs*32..+32] (4 n-tiles)
// PV phase: warp(mt, nh=w>>2) owns O[mt*16..+16][nh*32..+32], 8 k-steps
// ---------------------------------------------------------------------------
#define QS_OFF   0
#define KS_OFF   (QS_OFF + BQ_*68)             // 4352
#define VS_OFF   (KS_OFF + 2*BKV_*68)          // 13056
#define SS_OFF   (VS_OFF + 2*BKV_*72)          // 22272
#define RSC_OFF  (SS_OFF + BQ_*68)             // 26624
#define RIV_OFF  (RSC_OFF + BQ_)
#define ATTN_SMEM_FLOATS (RIV_OFF + BQ_)       // 26752 floats
#define ATTN_SMEM_BYTES  (ATTN_SMEM_FLOATS * 4) // 107008 B

__global__ __launch_bounds__(256, 2) void attn_kernel() {
    extern __shared__ float smx[];
    float (*Qs)[68] = (float(*)[68])(smx + QS_OFF);
    float (*Ks)[68] = (float(*)[68])(smx + KS_OFF);   // [2*64][68]
    float (*Vs)[72] = (float(*)[72])(smx + VS_OFF);   // [2*64][72]
    float (*Ss)[68] = (float(*)[68])(smx + SS_OFF);
    float* rowscale = smx + RSC_OFF;
    float* rowinv   = smx + RIV_OFF;

    const uint32_t ks_base = smem_u32(&Ks[0][0]);
    const uint32_t vs_base = smem_u32(&Vs[0][0]);

    const int qt = blockIdx.x, h = blockIdx.y, b = blockIdx.z;
    const int tid = threadIdx.x, wid = tid >> 5, lane = tid & 31;
    const int g = lane >> 2, tig = lane & 3;
    const int mt = wid & 3, nh = wid >> 2;     // nh in {0,1}
    const int qm = mt * 16;
    const int rr = tid >> 2, qd = tid & 3;     // softmax: quad per row, 16 vals
    const int hoff = h * HD_;
    const int* __restrict__ rows = g_kvrows + b * TK_;

    // Load Q tile (pre-scaled by 1/8)
    for (int idx = tid; idx < BQ_*HD_; idx += 256) {
        int r = idx >> 6, d = idx & 63;
        Qs[r][d] = g_Q[(size_t)(b*T_ + qt*BQ_ + r) * C_ + hoff + d] * 0.125f;
    }
    __syncthreads();

    // cp.async gather of one 64-row chunk into buffer `buf`
    const int pj = tid >> 4, pd = (tid & 15) << 2;
    auto prefetch = [&](int ch, int buf) {
        #pragma unroll
        for (int t = 0; t < 4; t++) {
            int j = pj + t*16;
            int src = __ldg(rows + ch*BKV_ + j);
            const float* gk = g_K + (size_t)src * C_ + hoff + pd;
            const float* gv = g_V + (size_t)src * C_ + hoff + pd;
            uint32_t sk = ks_base + (uint32_t)(((buf*BKV_ + j)*68 + pd) * 4);
            uint32_t sv = vs_base + (uint32_t)(((buf*BKV_ + j)*72 + pd) * 4);
            CP_ASYNC16(sk, gk);
            CP_ASYNC16(sv, gv);
        }
        CP_COMMIT();
    };

    prefetch(0, 0);

    // Hoist Q fragment VALUES (smalls recomputed per use)
    float qv[8][4];
    #pragma unroll
    for (int ks = 0; ks < 8; ks++) {
        qv[ks][0] = Qs[qm + g    ][ks*8 + tig    ];
        qv[ks][1] = Qs[qm + g + 8][ks*8 + tig    ];
        qv[ks][2] = Qs[qm + g    ][ks*8 + tig + 4];
        qv[ks][3] = Qs[qm + g + 8][ks*8 + tig + 4];
    }

    float pacc[4][4];
    #pragma unroll
    for (int t = 0; t < 4; t++)
        #pragma unroll
        for (int v = 0; v < 4; v++) pacc[t][v] = 0.f;
    float m = -1e30f, l = 0.f;

    for (int ch = 0; ch < NCH_; ch++) {
        const int cur = ch & 1;
        __syncthreads();                    // prior PV reads of buf 1-cur done
        if (ch + 1 < NCH_) { prefetch(ch + 1, 1 - cur); CP_WAIT(1); }
        else               { CP_WAIT(0); }
        __syncthreads();                    // cur buffer visible to all

        const float (*Kc)[68] = Ks + cur*BKV_;
        const float (*Vc)[72] = Vs + cur*BKV_;

        // ---- S = Q @ K^T  (3xTF32): 64x64 tile, warp covers 16x32 ----
        float sacc[4][4];
        #pragma unroll
        for (int nt = 0; nt < 4; nt++)
            #pragma unroll
            for (int v = 0; v < 4; v++) sacc[nt][v] = 0.f;
        #pragma unroll
        for (int ks = 0; ks < 8; ks++) {
            uint32_t qb[4], qs[4];
            #pragma unroll
            for (int i = 0; i < 4; i++) {
                qb[i] = __float_as_uint(qv[ks][i]);
                qs[i] = tf32_small(qv[ks][i]);
            }
            #pragma unroll
            for (int nt = 0; nt < 4; nt++) {
                const int jn = nh*32 + nt*8 + g;
                float w0 = Kc[jn][ks*8 + tig    ];
                float w1 = Kc[jn][ks*8 + tig + 4];
                uint32_t kb[2] = { __float_as_uint(w0), __float_as_uint(w1) };
                uint32_t ksm[2] = { tf32_small(w0), tf32_small(w1) };
                mma_tf32(sacc[nt], qb, kb);
                mma_tf32(sacc[nt], qb, ksm);
                mma_tf32(sacc[nt], qs, kb);
            }
        }
        #pragma unroll
        for (int nt = 0; nt < 4; nt++) {
            *(float2*)&Ss[qm + g    ][nh*32 + nt*8 + 2*tig] = make_float2(sacc[nt][0], sacc[nt][1]);
            *(float2*)&Ss[qm + g + 8][nh*32 + nt*8 + 2*tig] = make_float2(sacc[nt][2], sacc[nt][3]);
        }
        __syncthreads();

        // ---- online softmax (fp32): quad per row, 16 scores each ----
        float sv[16];
        #pragma unroll
        for (int w = 0; w < 16; w++) sv[w] = Ss[rr][qd*16 + w];
        float cm = sv[0];
        #pragma unroll
        for (int w = 1; w < 16; w++) cm = fmaxf(cm, sv[w]);
        cm = fmaxf(cm, __shfl_xor_sync(0xffffffffu, cm, 1));
        cm = fmaxf(cm, __shfl_xor_sync(0xffffffffu, cm, 2));
        float mn   = fmaxf(m, cm);
        float corr = __expf(m - mn);
        float ps   = 0.f;
        #pragma unroll
        for (int w = 0; w < 16; w++) {
            float p = __expf(sv[w] - mn);
            ps += p;
            Ss[rr][qd*16 + w] = p;
        }
        ps += __shfl_xor_sync(0xffffffffu, ps, 1);
        ps += __shfl_xor_sync(0xffffffffu, ps, 2);
        l = l * corr + ps;
        m = mn;
        if (qd == 0) rowscale[rr] = corr;
        __syncthreads();

        // ---- O = O*corr + P @ V  (3xTF32): P 64x64, 8 k-steps ----
        const float s_g  = rowscale[qm + g];
        const float s_g8 = rowscale[qm + g + 8];
        #pragma unroll
        for (int nt = 0; nt < 4; nt++) {
            pacc[nt][0] *= s_g;  pacc[nt][1] *= s_g;
            pacc[nt][2] *= s_g8; pacc[nt][3] *= s_g8;
        }
        #pragma unroll
        for (int ks = 0; ks < 8; ks++) {
            float p0 = Ss[qm + g    ][ks*8 + tig    ];
            float p1 = Ss[qm + g + 8][ks*8 + tig    ];
            float p2 = Ss[qm + g    ][ks*8 + tig + 4];
            float p3 = Ss[qm + g + 8][ks*8 + tig + 4];
            uint32_t pb[4] = { __float_as_uint(p0), __float_as_uint(p1),
                               __float_as_uint(p2), __float_as_uint(p3) };
            uint32_t psm[4] = { tf32_small(p0), tf32_small(p1),
                                tf32_small(p2), tf32_small(p3) };
            #pragma unroll
            for (int nt = 0; nt < 4; nt++) {
                float w0 = Vc[ks*8 + tig    ][nh*32 + nt*8 + g];
                float w1 = Vc[ks*8 + tig + 4][nh*32 + nt*8 + g];
                uint32_t vb[2] = { __float_as_uint(w0), __float_as_uint(w1) };
                uint32_t vsm[2] = { tf32_small(w0), tf32_small(w1) };
                mma_tf32(pacc[nt], pb,  vb);
                mma_tf32(pacc[nt], pb,  vsm);
                mma_tf32(pacc[nt], psm, vb);
            }
        }
    }

    if (qd == 0) rowinv[rr] = 1.f / l;
    __syncthreads();

    const float i_g  = rowinv[qm + g];
    const float i_g8 = rowinv[qm + g + 8];
    const size_t orow0 = (size_t)(b*T_ + qt*BQ_ + qm + g) * C_ + hoff;
    #pragma unroll
    for (int nt = 0; nt < 4; nt++) {
        const int col = nh*32 + nt*8 + 2*tig;
        *(float2*)&g_AO[orow0 + col]          = make_float2(pacc[nt][0]*i_g,  pacc[nt][1]*i_g);
        *(float2*)&g_AO[orow0 + 8*C_ + col]   = make_float2(pacc[nt][2]*i_g8, pacc[nt][3]*i_g8);
    }
}

// ---------------------------------------------------------------------------
extern "C" void kernel_launch(void* const* d_in, const int* in_sizes, int n_in,
                              void* d_out, int out_size) {
    const float* hs  = (const float*)d_in[0];
    const float* Wq  = (const float*)d_in[1];
    const float* Wk  = (const float*)d_in[2];
    const float* Wv  = (const float*)d_in[3];
    const float* Wo  = (const float*)d_in[4];
    const float* bo  = (const float*)d_in[5];
    const void*  idx = d_in[6];
    float* out = (float*)d_out;

    float *Qp, *Kp, *Vp, *Ap;
    cudaGetSymbolAddress((void**)&Qp, g_Q);
    cudaGetSymbolAddress((void**)&Kp, g_K);
    cudaGetSymbolAddress((void**)&Vp, g_V);
    cudaGetSymbolAddress((void**)&Ap, g_AO);

    // Host-side attribute set; idempotent, called unconditionally.
    cudaFuncSetAttribute(attn_kernel,
                         cudaFuncAttributeMaxDynamicSharedMemorySize,
                         ATTN_SMEM_BYTES);

    build_kv_kernel<<<B_, 256>>>(idx);

    dim3 gq(C_/128, (B_*T_)/128, 3);    // (10, 45, 3)
    gemm_qkv_kernel<<<gq, 256>>>(hs, Wq, Wk, Wv, Qp, Kp, Vp);

    dim3 ga(T_/BQ_, H_, B_);            // (9, 20, 10)
    attn_kernel<<<ga, 256, ATTN_SMEM_BYTES>>>();

    dim3 gg(C_/128, (B_*T_)/128);       // (10, 45)
    gemm_o_kernel<<<gg, 256>>>(Ap, Wo, bo, out);
}

// round 12
// speedup vs baseline: 1.0046x; 1.0046x over previous
#include <cuda_runtime.h>
#include <cstdint>

// Problem constants
#define B_    10      // 2 * IMG_COUNT sequences
#define T_    576     // tokens per sequence
#define C_    1280    // channels
#define H_    20      // heads
#define HD_   64      // head dim
#define P_    5       // plates
#define NSEL_ 288     // selected tokens per plate
#define TK_   1728    // kv length
#define BQ_   64
#define BKV_  32
#define NCH_  (TK_/BKV_)   // 54

// Scratch (device globals: allocation APIs are forbidden)
__device__ __align__(256) float g_Q [B_*T_*C_];
__device__ __align__(256) float g_K [B_*T_*C_];
__device__ __align__(256) float g_V [B_*T_*C_];
__device__ __align__(256) float g_AO[B_*T_*C_];
__device__ int g_kvrows[B_*TK_];

// ---------------------------------------------------------------------------
// Portable tf32 tensor-core MMA (sm_80+). HW reads operand bits[31:13] (RZ
// truncation) -- exploited for the big/small 3xTF32 split.
// ---------------------------------------------------------------------------
__device__ __forceinline__ void mma_tf32(float* c, const uint32_t* a, const uint32_t* b) {
    asm volatile(
        "mma.sync.aligned.m16n8k8.row.col.f32.tf32.tf32.f32 "
        "{%0,%1,%2,%3}, {%4,%5,%6,%7}, {%8,%9}, {%0,%1,%2,%3};"
        : "+f"(c[0]), "+f"(c[1]), "+f"(c[2]), "+f"(c[3])
        : "r"(a[0]), "r"(a[1]), "r"(a[2]), "r"(a[3]), "r"(b[0]), "r"(b[1]));
}

__device__ __forceinline__ uint32_t tf32_small(float v) {
    uint32_t big = __float_as_uint(v) & 0xFFFFE000u;
    return __float_as_uint(v - __uint_as_float(big));
}

__device__ __forceinline__ uint32_t smem_u32(const void* p) {
    uint32_t a;
    asm("{ .reg .u64 t; cvta.to.shared.u64 t, %1; cvt.u32.u64 %0, t; }" : "=r"(a) : "l"(p));
    return a;
}

#define CP_ASYNC16(smem, gptr) \
    asm volatile("cp.async.cg.shared.global [%0], [%1], 16;" :: "r"(smem), "l"(gptr))
#define CP_COMMIT()  asm volatile("cp.async.commit_group;" ::: "memory")
#define CP_WAIT(n)   asm volatile("cp.async.wait_group %0;" :: "n"(n) : "memory")

// ---------------------------------------------------------------------------
// Build per-(s,i) KV row index table (int64/int32 runtime detect).
// ---------------------------------------------------------------------------
__global__ void build_kv_kernel(const void* __restrict__ idx_raw) {
    const int*       i32 = (const int*)idx_raw;
    const long long* i64 = (const long long*)idx_raw;
    bool is64 = true;
    #pragma unroll 8
    for (int k = 0; k < 64; k++) {
        if (i32[2*k + 1] != 0) { is64 = false; break; }
    }
    const int b = blockIdx.x;
    const int s = b / P_, i = b % P_;
    for (int m = threadIdx.x; m < TK_; m += blockDim.x) {
        int row;
        if (m < (P_-1)*NSEL_) {
            int prel = m / NSEL_;
            int p    = prel + (prel >= i ? 1 : 0);
            int j    = m - prel * NSEL_;
            int tok  = is64 ? (int)i64[p*NSEL_ + j] : i32[p*NSEL_ + j];
            row = (s*P_ + p) * T_ + tok;
        } else {
            row = (s*P_ + i) * T_ + (m - (P_-1)*NSEL_);
        }
        g_kvrows[b*TK_ + m] = row;
    }
}

// ---------------------------------------------------------------------------
// 3xTF32 GEMM core, 128x64 CTA tile (8 warps x 32x32 warp tile), BK=32.
// ~110 regs -> 2 CTAs/SM under __launch_bounds__(256,2): 4 warps/SMSP to
// hide LDS->split->mma dependency stalls (R5-R10 profile: tensor=65% @ 1 CTA).
// ---------------------------------------------------------------------------
__device__ __forceinline__ void gemm_tile_body(
    const float* __restrict__ A, const float* __restrict__ Bw,
    const float* __restrict__ bias, float* __restrict__ Y,
    int N, int K, int m0, int n0)
{
    __shared__ float As[128][36];
    __shared__ float Bs[64][36];

    const int tid = threadIdx.x, wid = tid >> 5, lane = tid & 31;
    const int g = lane >> 2, tig = lane & 3;
    const int wm = (wid & 3) * 32, wn = (wid >> 2) * 32;
    const int NST = K >> 5;

    // loaders: A 128x32 (16 floats/thread), B 64x32 (8 floats/thread)
    const int rA = tid >> 1, hA = tid & 1;
    const int rB = tid >> 2, qB = tid & 3;
    const float* pA = A  + (size_t)(m0 + rA) * K + hA * 16;
    const float* pB = Bw + (size_t)(n0 + rB) * K + qB * 8;

    float acc[8][4];
    #pragma unroll
    for (int t = 0; t < 8; t++)
        #pragma unroll
        for (int v = 0; v < 4; v++) acc[t][v] = 0.f;

    float4 ra[4], rb[2];
    #pragma unroll
    for (int j = 0; j < 4; j++) ra[j] = *(const float4*)(pA + j*4);
    #pragma unroll
    for (int j = 0; j < 2; j++) rb[j] = *(const float4*)(pB + j*4);

    for (int s = 0; s < NST; s++) {
        #pragma unroll
        for (int j = 0; j < 4; j++) *(float4*)&As[rA][hA*16 + j*4] = ra[j];
        #pragma unroll
        for (int j = 0; j < 2; j++) *(float4*)&Bs[rB][qB*8 + j*4] = rb[j];
        __syncthreads();

        if (s + 1 < NST) {
            const float* a2 = pA + (s+1) * 32;
            const float* b2 = pB + (s+1) * 32;
            #pragma unroll
            for (int j = 0; j < 4; j++) ra[j] = *(const float4*)(a2 + j*4);
            #pragma unroll
            for (int j = 0; j < 2; j++) rb[j] = *(const float4*)(b2 + j*4);
        }

        #pragma unroll
        for (int kb = 0; kb < 32; kb += 8) {
            uint32_t af[2][4], asm_[2][4], bf[4][2], bsm[4][2];
            #pragma unroll
            for (int mt = 0; mt < 2; mt++) {
                const int rb0 = wm + mt*16 + g;
                float v0 = As[rb0    ][kb + tig    ];
                float v1 = As[rb0 + 8][kb + tig    ];
                float v2 = As[rb0    ][kb + tig + 4];
                float v3 = As[rb0 + 8][kb + tig + 4];
                af[mt][0] = __float_as_uint(v0); asm_[mt][0] = tf32_small(v0);
                af[mt][1] = __float_as_uint(v1); asm_[mt][1] = tf32_small(v1);
                af[mt][2] = __float_as_uint(v2); asm_[mt][2] = tf32_small(v2);
                af[mt][3] = __float_as_uint(v3); asm_[mt][3] = tf32_small(v3);
            }
            #pragma unroll
            for (int nt = 0; nt < 4; nt++) {
                const int nb0 = wn + nt*8 + g;
                float w0 = Bs[nb0][kb + tig    ];
                float w1 = Bs[nb0][kb + tig + 4];
                bf[nt][0] = __float_as_uint(w0); bsm[nt][0] = tf32_small(w0);
                bf[nt][1] = __float_as_uint(w1); bsm[nt][1] = tf32_small(w1);
            }
            #pragma unroll
            for (int mt = 0; mt < 2; mt++)
                #pragma unroll
                for (int nt = 0; nt < 4; nt++) {
                    float* c = acc[mt*4 + nt];
                    mma_tf32(c, af[mt],   bf[nt]);
                    mma_tf32(c, af[mt],   bsm[nt]);
                    mma_tf32(c, asm_[mt], bf[nt]);
                }
        }
        __syncthreads();
    }

    #pragma unroll
    for (int mt = 0; mt < 2; mt++) {
        #pragma unroll
        for (int nt = 0; nt < 4; nt++) {
            const float* c = acc[mt*4 + nt];
            const int row = m0 + wm + mt*16 + g;
            const int col = n0 + wn + nt*8 + 2*tig;
            float b0c = 0.f, b1c = 0.f;
            if (bias) { b0c = bias[col]; b1c = bias[col + 1]; }
            float2 v0 = make_float2(c[0] + b0c, c[1] + b1c);
            float2 v1 = make_float2(c[2] + b0c, c[3] + b1c);
            *(float2*)(Y + (size_t)row       * N + col) = v0;
            *(float2*)(Y + (size_t)(row + 8) * N + col) = v1;
        }
    }
}

// Fused Q/K/V projection: blockIdx.z selects weight + destination.
__global__ __launch_bounds__(256, 2) void gemm_qkv_kernel(
    const float* __restrict__ hs,
    const float* __restrict__ Wq, const float* __restrict__ Wk,
    const float* __restrict__ Wv,
    float* __restrict__ Qp, float* __restrict__ Kp, float* __restrict__ Vp)
{
    const int z = blockIdx.z;
    const float* Bw = (z == 0) ? Wq : (z == 1) ? Wk : Wv;
    float*       Y  = (z == 0) ? Qp : (z == 1) ? Kp : Vp;
    gemm_tile_body(hs, Bw, nullptr, Y, C_, C_, blockIdx.y * 128, blockIdx.x * 64);
}

// Output projection (with bias).
__global__ __launch_bounds__(256, 2) void gemm_o_kernel(
    const float* __restrict__ A, const float* __restrict__ Wo,
    const float* __restrict__ bo, float* __restrict__ Y)
{
    gemm_tile_body(A, Wo, bo, Y, C_, C_, blockIdx.y * 128, blockIdx.x * 64);
}

// ---------------------------------------------------------------------------
// Tensor-core flash attention (3xTF32), BKV=32, cp.async double-buffer.
// EXACT revert to the R8 configuration that measured 1978 us total.
// Dynamic smem layout (floats):
//   Qs[64][68] | Ks[2][32][68] | Vs[2][32][72] | Ss[64][36]
//   | rowscale[64] | rowinv[64] | rows_s[1728 ints]
// ---------------------------------------------------------------------------
#define QS_OFF   0
#define KS_OFF   (QS_OFF + BQ_*68)            // 4352
#define VS_OFF   (KS_OFF + 2*BKV_*68)          // 8704
#define SS_OFF   (VS_OFF + 2*BKV_*72)          // 13312
#define RSC_OFF  (SS_OFF + BQ_*36)             // 15616
#define RIV_OFF  (RSC_OFF + BQ_)
#define ROWS_OFF (RIV_OFF + BQ_)
#define ATTN_SMEM_FLOATS (ROWS_OFF + TK_)      // 19472 floats = 77888 B
#define ATTN_SMEM_BYTES  (ATTN_SMEM_FLOATS * 4)

__global__ __launch_bounds__(256, 2) void attn_kernel() {
    extern __shared__ float smx[];
    float (*Qs)[68] = (float(*)[68])(smx + QS_OFF);
    float (*Ks)[68] = (float(*)[68])(smx + KS_OFF);   // [2*32][68]
    float (*Vs)[72] = (float(*)[72])(smx + VS_OFF);   // [2*32][72]
    float (*Ss)[36] = (float(*)[36])(smx + SS_OFF);
    float* rowscale = smx + RSC_OFF;
    float* rowinv   = smx + RIV_OFF;
    int*   rows_s   = (int*)(smx + ROWS_OFF);

    const uint32_t ks_base = smem_u32(&Ks[0][0]);
    const uint32_t vs_base = smem_u32(&Vs[0][0]);

    const int qt = blockIdx.x, h = blockIdx.y, b = blockIdx.z;
    const int tid = threadIdx.x, wid = tid >> 5, lane = tid & 31;
    const int g = lane >> 2, tig = lane & 3;
    const int mt = wid & 3, nh = wid >> 2;
    const int qm = mt * 16;
    const int rr = tid >> 2, qd = tid & 3;
    const int hoff = h * HD_;

    // Stage row indices + Q tile
    for (int m = tid; m < TK_; m += 256) rows_s[m] = g_kvrows[b*TK_ + m];
    for (int idx = tid; idx < BQ_*HD_; idx += 256) {
        int r = idx >> 6, d = idx & 63;
        Qs[r][d] = g_Q[(size_t)(b*T_ + qt*BQ_ + r) * C_ + hoff + d] * 0.125f;
    }
    __syncthreads();

    // cp.async gather of one chunk into buffer `buf`
    const int pj = tid >> 4, pd = (tid & 15) << 2;   // t=0 mapping; t=1 adds 16 rows
    auto prefetch = [&](int ch, int buf) {
        #pragma unroll
        for (int t = 0; t < 2; t++) {
            int j = pj + t*16;
            int src = rows_s[ch*BKV_ + j];
            const float* gk = g_K + (size_t)src * C_ + hoff + pd;
            const float* gv = g_V + (size_t)src * C_ + hoff + pd;
            uint32_t sk = ks_base + (uint32_t)(((buf*BKV_ + j)*68 + pd) * 4);
            uint32_t sv = vs_base + (uint32_t)(((buf*BKV_ + j)*72 + pd) * 4);
            CP_ASYNC16(sk, gk);
            CP_ASYNC16(sv, gv);
        }
        CP_COMMIT();
    };

    prefetch(0, 0);

    // Hoist Q fragment VALUES
    float qv[8][4];
    #pragma unroll
    for (int ks = 0; ks < 8; ks++) {
        qv[ks][0] = Qs[qm + g    ][ks*8 + tig    ];
        qv[ks][1] = Qs[qm + g + 8][ks*8 + tig    ];
        qv[ks][2] = Qs[qm + g    ][ks*8 + tig + 4];
        qv[ks][3] = Qs[qm + g + 8][ks*8 + tig + 4];
    }

    float pacc[4][4];
    #pragma unroll
    for (int t = 0; t < 4; t++)
        #pragma unroll
        for (int v = 0; v < 4; v++) pacc[t][v] = 0.f;
    float m = -1e30f, l = 0.f;

    for (int ch = 0; ch < NCH_; ch++) {
        const int cur = ch & 1;
        __syncthreads();                    // prior PV reads of buf 1-cur done
        if (ch + 1 < NCH_) { prefetch(ch + 1, 1 - cur); CP_WAIT(1); }
        else               { CP_WAIT(0); }
        __syncthreads();                    // cur buffer visible to all

        const float (*Kc)[68] = Ks + cur*BKV_;
        const float (*Vc)[72] = Vs + cur*BKV_;

        // ---- S = Q @ K^T  (3xTF32) ----
        float sacc[2][4];
        #pragma unroll
        for (int nt = 0; nt < 2; nt++)
            #pragma unroll
            for (int v = 0; v < 4; v++) sacc[nt][v] = 0.f;
        #pragma unroll
        for (int ks = 0; ks < 8; ks++) {
            uint32_t qb[4], qs[4];
            #pragma unroll
            for (int i = 0; i < 4; i++) {
                qb[i] = __float_as_uint(qv[ks][i]);
                qs[i] = tf32_small(qv[ks][i]);
            }
            #pragma unroll
            for (int nt = 0; nt < 2; nt++) {
                const int jn = nh*16 + nt*8 + g;
                float w0 = Kc[jn][ks*8 + tig    ];
                float w1 = Kc[jn][ks*8 + tig + 4];
                uint32_t kb[2] = { __float_as_uint(w0), __float_as_uint(w1) };
                uint32_t ksm[2] = { tf32_small(w0), tf32_small(w1) };
                mma_tf32(sacc[nt], qb, kb);
                mma_tf32(sacc[nt], qb, ksm);
                mma_tf32(sacc[nt], qs, kb);
            }
        }
        #pragma unroll
        for (int nt = 0; nt < 2; nt++) {
            *(float2*)&Ss[qm + g    ][nh*16 + nt*8 + 2*tig] = make_float2(sacc[nt][0], sacc[nt][1]);
            *(float2*)&Ss[qm + g + 8][nh*16 + nt*8 + 2*tig] = make_float2(sacc[nt][2], sacc[nt][3]);
        }
        __syncthreads();

        // ---- online softmax (fp32, quad per row) ----
        float sv[8];
        #pragma unroll
        for (int w = 0; w < 8; w++) sv[w] = Ss[rr][qd*8 + w];
        float cm = sv[0];
        #pragma unroll
        for (int w = 1; w < 8; w++) cm = fmaxf(cm, sv[w]);
        cm = fmaxf(cm, __shfl_xor_sync(0xffffffffu, cm, 1));
        cm = fmaxf(cm, __shfl_xor_sync(0xffffffffu, cm, 2));
        float mn   = fmaxf(m, cm);
        float corr = __expf(m - mn);
        float ps   = 0.f;
        #pragma unroll
        for (int w = 0; w < 8; w++) {
            float p = __expf(sv[w] - mn);
            ps += p;
            Ss[rr][qd*8 + w] = p;
        }
        ps += __shfl_xor_sync(0xffffffffu, ps, 1);
        ps += __shfl_xor_sync(0xffffffffu, ps, 2);
        l = l * corr + ps;
        m = mn;
        if (qd == 0) rowscale[rr] = corr;
        __syncthreads();

        // ---- O = O*corr + P @ V  (3xTF32) ----
        const float s_g  = rowscale[qm + g];
        const float s_g8 = rowscale[qm + g + 8];
        #pragma unroll
        for (int nt = 0; nt < 4; nt++) {
            pacc[nt][0] *= s_g;  pacc[nt][1] *= s_g;
            pacc[nt][2] *= s_g8; pacc[nt][3] *= s_g8;
        }
        #pragma unroll
        for (int ks = 0; ks < 4; ks++) {
            float p0 = Ss[qm + g    ][ks*8 + tig    ];
            float p1 = Ss[qm + g + 8][ks*8 + tig    ];
            float p2 = Ss[qm + g    ][ks*8 + tig + 4];
            float p3 = Ss[qm + g + 8][ks*8 + tig + 4];
            uint32_t pb[4] = { __float_as_uint(p0), __float_as_uint(p1),
                               __float_as_uint(p2), __float_as_uint(p3) };
            uint32_t psm[4] = { tf32_small(p0), tf32_small(p1),
                                tf32_small(p2), tf32_small(p3) };
            #pragma unroll
            for (int nt = 0; nt < 4; nt++) {
                float w0 = Vc[ks*8 + tig    ][nh*32 + nt*8 + g];
                float w1 = Vc[ks*8 + tig + 4][nh*32 + nt*8 + g];
                uint32_t vb[2] = { __float_as_uint(w0), __float_as_uint(w1) };
                uint32_t vsm[2] = { tf32_small(w0), tf32_small(w1) };
                mma_tf32(pacc[nt], pb,  vb);
                mma_tf32(pacc[nt], pb,  vsm);
                mma_tf32(pacc[nt], psm, vb);
            }
        }
    }

    if (qd == 0) rowinv[rr] = 1.f / l;
    __syncthreads();

    const float i_g  = rowinv[qm + g];
    const float i_g8 = rowinv[qm + g + 8];
    const size_t orow0 = (size_t)(b*T_ + qt*BQ_ + qm + g) * C_ + hoff;
    #pragma unroll
    for (int nt = 0; nt < 4; nt++) {
        const int col = nh*32 + nt*8 + 2*tig;
        *(float2*)&g_AO[orow0 + col]          = make_float2(pacc[nt][0]*i_g,  pacc[nt][1]*i_g);
        *(float2*)&g_AO[orow0 + 8*C_ + col]   = make_float2(pacc[nt][2]*i_g8, pacc[nt][3]*i_g8);
    }
}

// ---------------------------------------------------------------------------
extern "C" void kernel_launch(void* const* d_in, const int* in_sizes, int n_in,
                              void* d_out, int out_size) {
    const float* hs  = (const float*)d_in[0];
    const float* Wq  = (const float*)d_in[1];
    const float* Wk  = (const float*)d_in[2];
    const float* Wv  = (const float*)d_in[3];
    const float* Wo  = (const float*)d_in[4];
    const float* bo  = (const float*)d_in[5];
    const void*  idx = d_in[6];
    float* out = (float*)d_out;

    float *Qp, *Kp, *Vp, *Ap;
    cudaGetSymbolAddress((void**)&Qp, g_Q);
    cudaGetSymbolAddress((void**)&Kp, g_K);
    cudaGetSymbolAddress((void**)&Vp, g_V);
    cudaGetSymbolAddress((void**)&Ap, g_AO);

    // Host-side attribute set; idempotent, called unconditionally.
    cudaFuncSetAttribute(attn_kernel,
                         cudaFuncAttributeMaxDynamicSharedMemorySize,
                         ATTN_SMEM_BYTES);

    build_kv_kernel<<<B_, 256>>>(idx);

    dim3 gq(C_/64, (B_*T_)/128, 3);     // (20, 45, 3) = 2700 CTAs
    gemm_qkv_kernel<<<gq, 256>>>(hs, Wq, Wk, Wv, Qp, Kp, Vp);

    dim3 ga(T_/BQ_, H_, B_);            // (9, 20, 10)
    attn_kernel<<<ga, 256, ATTN_SMEM_BYTES>>>();

    dim3 gg(C_/64, (B_*T_)/128);        // (20, 45)
    gemm_o_kernel<<<gg, 256>>>(Ap, Wo, bo, out);
}

// round 15
// speedup vs baseline: 1.2077x; 1.2022x over previous
#include <cuda_runtime.h>
#include <cstdint>

// Problem constants
#define B_    10
#define T_    576
#define C_    1280
#define H_    20
#define HD_   64
#define P_    5
#define NSEL_ 288
#define TK_   1728
#define BQ_   64
#define BKV_  32
#define NCH_  (TK_/BKV_)   // 54

// Scratch (device globals: allocation APIs are forbidden)
__device__ __align__(256) float    g_Q  [B_*T_*C_];
__device__ __align__(256) uint32_t g_Khi[B_*T_*C_/2];   // bf16 pair-packed (d-pairs)
__device__ __align__(256) uint32_t g_Klo[B_*T_*C_/2];   // residual plane
__device__ __align__(256) float    g_V  [B_*T_*C_];
__device__ __align__(256) float    g_AO [B_*T_*C_];
__device__ int g_kvrows[B_*TK_];

// ---------------------------------------------------------------------------
// MMA helpers
// ---------------------------------------------------------------------------
__device__ __forceinline__ void mma_tf32(float* c, const uint32_t* a, const uint32_t* b) {
    asm volatile(
        "mma.sync.aligned.m16n8k8.row.col.f32.tf32.tf32.f32 "
        "{%0,%1,%2,%3}, {%4,%5,%6,%7}, {%8,%9}, {%0,%1,%2,%3};"
        : "+f"(c[0]), "+f"(c[1]), "+f"(c[2]), "+f"(c[3])
        : "r"(a[0]), "r"(a[1]), "r"(a[2]), "r"(a[3]), "r"(b[0]), "r"(b[1]));
}

__device__ __forceinline__ void mma_bf16(float* c, const uint32_t* a, uint32_t b0, uint32_t b1) {
    asm volatile(
        "mma.sync.aligned.m16n8k16.row.col.f32.bf16.bf16.f32 "
        "{%0,%1,%2,%3}, {%4,%5,%6,%7}, {%8,%9}, {%0,%1,%2,%3};"
        : "+f"(c[0]), "+f"(c[1]), "+f"(c[2]), "+f"(c[3])
        : "r"(a[0]), "r"(a[1]), "r"(a[2]), "r"(a[3]), "r"(b0), "r"(b1));
}

__device__ __forceinline__ uint32_t tf32_small(float v) {
    uint32_t big = __float_as_uint(v) & 0xFFFFE000u;
    return __float_as_uint(v - __uint_as_float(big));
}

// Split (x0,x1) into packed bf16 hi pair and residual lo pair.
// PTX cvt.bf16x2: first source -> HIGH half; low half = first element (x0).
__device__ __forceinline__ uint2 bf16x2_split2(float x0, float x1) {
    uint32_t h, l;
    asm("cvt.rn.bf16x2.f32 %0, %1, %2;" : "=r"(h) : "f"(x1), "f"(x0));
    float h0 = __uint_as_float(h << 16);
    float h1 = __uint_as_float(h & 0xFFFF0000u);
    float r0 = x0 - h0, r1 = x1 - h1;
    asm("cvt.rn.bf16x2.f32 %0, %1, %2;" : "=r"(l) : "f"(r1), "f"(r0));
    return make_uint2(h, l);
}

__device__ __forceinline__ uint32_t smem_u32(const void* p) {
    uint32_t a;
    asm("{ .reg .u64 t; cvta.to.shared.u64 t, %1; cvt.u32.u64 %0, t; }" : "=r"(a) : "l"(p));
    return a;
}

#define CP_ASYNC16(smem, gptr) \
    asm volatile("cp.async.cg.shared.global [%0], [%1], 16;" :: "r"(smem), "l"(gptr))
#define CP_COMMIT()  asm volatile("cp.async.commit_group;" ::: "memory")
#define CP_WAIT(n)   asm volatile("cp.async.wait_group %0;" :: "n"(n) : "memory")

// ---------------------------------------------------------------------------
// Build per-(s,i) KV row index table (int64/int32 runtime detect).
// ---------------------------------------------------------------------------
__global__ void build_kv_kernel(const void* __restrict__ idx_raw) {
    const int*       i32 = (const int*)idx_raw;
    const long long* i64 = (const long long*)idx_raw;
    bool is64 = true;
    #pragma unroll 8
    for (int k = 0; k < 64; k++) {
        if (i32[2*k + 1] != 0) { is64 = false; break; }
    }
    const int b = blockIdx.x;
    const int s = b / P_, i = b % P_;
    for (int m = threadIdx.x; m < TK_; m += blockDim.x) {
        int row;
        if (m < (P_-1)*NSEL_) {
            int prel = m / NSEL_;
            int p    = prel + (prel >= i ? 1 : 0);
            int j    = m - prel * NSEL_;
            int tok  = is64 ? (int)i64[p*NSEL_ + j] : i32[p*NSEL_ + j];
            row = (s*P_ + p) * T_ + tok;
        } else {
            row = (s*P_ + i) * T_ + (m - (P_-1)*NSEL_);
        }
        g_kvrows[b*TK_ + m] = row;
    }
}

// ---------------------------------------------------------------------------
// bf16x2 split-precision GEMM: Y = A @ Bw^T (+bias). 128x128 CTA tile,
// 8 warps x 64x32 warp tile, BK=32 (2 x K=16 mma steps per stage).
// Loader converts fp32 -> bf16 hi/lo pair planes in smem; inner loop is
// 3 mmas per (mt,nt) per K=16 (h*h + h*l + l*h; l*l ~2^-16 dropped).
// kmode: write output as bf16 hi/lo planes (for K) instead of fp32.
// ---------------------------------------------------------------------------
__device__ __forceinline__ void gemm_tile_body(
    const float* __restrict__ A, const float* __restrict__ Bw,
    const float* __restrict__ bias, float* __restrict__ Y,
    uint32_t* __restrict__ khi, uint32_t* __restrict__ klo, int kmode,
    int N, int K, int m0, int n0)
{
    __shared__ uint32_t Ahi[128][20];   // 16 d-pairs + pad (bank: 20g+tig distinct)
    __shared__ uint32_t Alo[128][20];
    __shared__ uint32_t Bhi[128][20];
    __shared__ uint32_t Blo[128][20];

    const int tid = threadIdx.x, wid = tid >> 5, lane = tid & 31;
    const int g = lane >> 2, tig = lane & 3;
    const int wm = (wid & 1) * 64, wn = (wid >> 1) * 32;
    const int NST = K >> 5;

    const int r = tid >> 1, half = tid & 1;
    const float* pA = A  + (size_t)(m0 + r) * K + half * 16;
    const float* pB = Bw + (size_t)(n0 + r) * K + half * 16;

    float acc[16][4];
    #pragma unroll
    for (int t = 0; t < 16; t++)
        #pragma unroll
        for (int v = 0; v < 4; v++) acc[t][v] = 0.f;

    float4 ra[4], rb[4];
    #pragma unroll
    for (int j = 0; j < 4; j++) {
        ra[j] = *(const float4*)(pA + j*4);
        rb[j] = *(const float4*)(pB + j*4);
    }

    for (int s = 0; s < NST; s++) {
        #pragma unroll
        for (int j = 0; j < 4; j++) {
            uint2 a0 = bf16x2_split2(ra[j].x, ra[j].y);
            uint2 a1 = bf16x2_split2(ra[j].z, ra[j].w);
            uint2 b0 = bf16x2_split2(rb[j].x, rb[j].y);
            uint2 b1 = bf16x2_split2(rb[j].z, rb[j].w);
            const int pc = half*8 + j*2;
            Ahi[r][pc] = a0.x;   Alo[r][pc] = a0.y;
            Ahi[r][pc+1] = a1.x; Alo[r][pc+1] = a1.y;
            Bhi[r][pc] = b0.x;   Blo[r][pc] = b0.y;
            Bhi[r][pc+1] = b1.x; Blo[r][pc+1] = b1.y;
        }
        __syncthreads();

        if (s + 1 < NST) {
            const float* a2 = pA + (s+1) * 32;
            const float* b2 = pB + (s+1) * 32;
            #pragma unroll
            for (int j = 0; j < 4; j++) {
                ra[j] = *(const float4*)(a2 + j*4);
                rb[j] = *(const float4*)(b2 + j*4);
            }
        }

        #pragma unroll
        for (int kb = 0; kb < 16; kb += 8) {      // 2 x K=16 steps
            uint32_t ah[4][4], al[4][4], bh[4][2], bl[4][2];
            #pragma unroll
            for (int mt = 0; mt < 4; mt++) {
                const int rb0 = wm + mt*16 + g;
                ah[mt][0] = Ahi[rb0    ][kb + tig];
                ah[mt][1] = Ahi[rb0 + 8][kb + tig];
                ah[mt][2] = Ahi[rb0    ][kb + tig + 4];
                ah[mt][3] = Ahi[rb0 + 8][kb + tig + 4];
                al[mt][0] = Alo[rb0    ][kb + tig];
                al[mt][1] = Alo[rb0 + 8][kb + tig];
                al[mt][2] = Alo[rb0    ][kb + tig + 4];
                al[mt][3] = Alo[rb0 + 8][kb + tig + 4];
            }
            #pragma unroll
            for (int nt = 0; nt < 4; nt++) {
                const int nb0 = wn + nt*8 + g;
                bh[nt][0] = Bhi[nb0][kb + tig];
                bh[nt][1] = Bhi[nb0][kb + tig + 4];
                bl[nt][0] = Blo[nb0][kb + tig];
                bl[nt][1] = Blo[nb0][kb + tig + 4];
            }
            #pragma unroll
            for (int mt = 0; mt < 4; mt++)
                #pragma unroll
                for (int nt = 0; nt < 4; nt++) {
                    float* c = acc[mt*4 + nt];
                    mma_bf16(c, ah[mt], bh[nt][0], bh[nt][1]);
                    mma_bf16(c, ah[mt], bl[nt][0], bl[nt][1]);
                    mma_bf16(c, al[mt], bh[nt][0], bh[nt][1]);
                }
        }
        __syncthreads();
    }

    #pragma unroll
    for (int mt = 0; mt < 4; mt++) {
        #pragma unroll
        for (int nt = 0; nt < 4; nt++) {
            const float* c = acc[mt*4 + nt];
            const int row = m0 + wm + mt*16 + g;
            const int col = n0 + wn + nt*8 + 2*tig;      // even
            if (kmode) {
                uint2 h0 = bf16x2_split2(c[0], c[1]);
                uint2 h1 = bf16x2_split2(c[2], c[3]);
                const size_t o0 = (size_t)row       * (N/2) + (col >> 1);
                const size_t o1 = (size_t)(row + 8) * (N/2) + (col >> 1);
                khi[o0] = h0.x; klo[o0] = h0.y;
                khi[o1] = h1.x; klo[o1] = h1.y;
            } else {
                float b0c = 0.f, b1c = 0.f;
                if (bias) { b0c = bias[col]; b1c = bias[col + 1]; }
                float2 v0 = make_float2(c[0] + b0c, c[1] + b1c);
                float2 v1 = make_float2(c[2] + b0c, c[3] + b1c);
                *(float2*)(Y + (size_t)row       * N + col) = v0;
                *(float2*)(Y + (size_t)(row + 8) * N + col) = v1;
            }
        }
    }
}

// Fused Q/K/V projection: z selects weight + destination (K -> bf16 planes).
__global__ __launch_bounds__(256) void gemm_qkv_kernel(
    const float* __restrict__ hs,
    const float* __restrict__ Wq, const float* __restrict__ Wk,
    const float* __restrict__ Wv,
    float* __restrict__ Qp, float* __restrict__ Vp,
    uint32_t* __restrict__ khi, uint32_t* __restrict__ klo)
{
    const int z = blockIdx.z;
    const float* Bw = (z == 0) ? Wq : (z == 1) ? Wk : Wv;
    float*       Y  = (z == 0) ? Qp : Vp;
    gemm_tile_body(hs, Bw, nullptr, Y, khi, klo, (z == 1) ? 1 : 0,
                   C_, C_, blockIdx.y * 128, blockIdx.x * 128);
}

__global__ __launch_bounds__(256) void gemm_o_kernel(
    const float* __restrict__ A, const float* __restrict__ Wo,
    const float* __restrict__ bo, float* __restrict__ Y)
{
    gemm_tile_body(A, Wo, bo, Y, nullptr, nullptr, 0,
                   C_, C_, blockIdx.y * 128, blockIdx.x * 128);
}

// ---------------------------------------------------------------------------
// Flash attention: S = Q@K^T in bf16x2 (half the mma of 3xTF32), softmax fp32,
// PV in 3xTF32 (fp32 V, unchanged proven path). K gathered as bf16 hi/lo
// planes via cp.async (half the bytes); V fp32 via cp.async.
// Dynamic smem (bytes):
//   Qs[64][68]f | Kh[2][32][36]u32 | Kl[2][32][36]u32 | Vs[2][32][72]f
//   | Ss[64][36]f | rowscale[64] | rowinv[64] | rows_s[1728]i
// ---------------------------------------------------------------------------
#define QS_OFF   0
#define KH_OFF   (QS_OFF + BQ_*68)             // floats-size units (u32 == 4B)
#define KL_OFF   (KH_OFF + 2*BKV_*36)
#define VS_OFF   (KL_OFF + 2*BKV_*36)
#define SS_OFF   (VS_OFF + 2*BKV_*72)
#define RSC_OFF  (SS_OFF + BQ_*36)
#define RIV_OFF  (RSC_OFF + BQ_)
#define ROWS_OFF (RIV_OFF + BQ_)
#define ATTN_SMEM_WORDS (ROWS_OFF + TK_)
#define ATTN_SMEM_BYTES (ATTN_SMEM_WORDS * 4)   // 70912 B -> 2 CTAs/SM

__global__ __launch_bounds__(256, 2) void attn_kernel() {
    extern __shared__ float smx[];
    float    (*Qs)[68] = (float(*)[68])(smx + QS_OFF);
    uint32_t (*Kh)[36] = (uint32_t(*)[36])(smx + KH_OFF);  // [2*32][36]
    uint32_t (*Kl)[36] = (uint32_t(*)[36])(smx + KL_OFF);
    float    (*Vs)[72] = (float(*)[72])(smx + VS_OFF);     // [2*32][72]
    float    (*Ss)[36] = (float(*)[36])(smx + SS_OFF);
    float* rowscale = smx + RSC_OFF;
    float* rowinv   = smx + RIV_OFF;
    int*   rows_s   = (int*)(smx + ROWS_OFF);

    const uint32_t kh_base = smem_u32(&Kh[0][0]);
    const uint32_t kl_base = smem_u32(&Kl[0][0]);
    const uint32_t vs_base = smem_u32(&Vs[0][0]);

    const int qt = blockIdx.x, h = blockIdx.y, b = blockIdx.z;
    const int tid = threadIdx.x, wid = tid >> 5, lane = tid & 31;
    const int g = lane >> 2, tig = lane & 3;
    const int mt = wid & 3, nh = wid >> 2;
    const int qm = mt * 16;
    const int rr = tid >> 2, qd = tid & 3;
    const int hoff = h * HD_;

    // Stage row indices + Q tile (pre-scaled by 1/8)
    for (int m = tid; m < TK_; m += 256) rows_s[m] = g_kvrows[b*TK_ + m];
    for (int idx = tid; idx < BQ_*HD_; idx += 256) {
        int r = idx >> 6, d = idx & 63;
        Qs[r][d] = g_Q[(size_t)(b*T_ + qt*BQ_ + r) * C_ + hoff + d] * 0.125f;
    }
    __syncthreads();

    // cp.async gather: K hi/lo planes (128B/row each) + V fp32 (256B/row).
    // thread -> j = tid>>3 (row), seg = tid&7. 4 cp16 per thread per chunk.
    const int pj = tid >> 3, seg = tid & 7;
    auto prefetch = [&](int ch, int buf) {
        int src = rows_s[ch*BKV_ + pj];
        const uint32_t* gkh = g_Khi + (size_t)src * (C_/2) + (hoff >> 1) + seg*4;
        const uint32_t* gkl = g_Klo + (size_t)src * (C_/2) + (hoff >> 1) + seg*4;
        const float*    gv  = g_V   + (size_t)src * C_ + hoff + seg*8;
        uint32_t skh = kh_base + (uint32_t)(((buf*BKV_ + pj)*36 + seg*4) * 4);
        uint32_t skl = kl_base + (uint32_t)(((buf*BKV_ + pj)*36 + seg*4) * 4);
        uint32_t sv  = vs_base + (uint32_t)(((buf*BKV_ + pj)*72 + seg*8) * 4);
        CP_ASYNC16(skh, gkh);
        CP_ASYNC16(skl, gkl);
        CP_ASYNC16(sv, gv);
        CP_ASYNC16(sv + 16, gv + 4);
        CP_COMMIT();
    };

    prefetch(0, 0);

    // Hoist Q fragments as bf16x2 hi/lo (m16n8k16 layout, 4 K-steps of 16 d)
    uint32_t qh[4][4], ql[4][4];
    #pragma unroll
    for (int ks = 0; ks < 4; ks++) {
        const int d0 = ks*16 + 2*tig;
        float2 x0 = *(float2*)&Qs[qm + g    ][d0];
        float2 x1 = *(float2*)&Qs[qm + g + 8][d0];
        float2 x2 = *(float2*)&Qs[qm + g    ][d0 + 8];
        float2 x3 = *(float2*)&Qs[qm + g + 8][d0 + 8];
        uint2 s0 = bf16x2_split2(x0.x, x0.y);
        uint2 s1 = bf16x2_split2(x1.x, x1.y);
        uint2 s2 = bf16x2_split2(x2.x, x2.y);
        uint2 s3 = bf16x2_split2(x3.x, x3.y);
        qh[ks][0] = s0.x; ql[ks][0] = s0.y;
        qh[ks][1] = s1.x; ql[ks][1] = s1.y;
        qh[ks][2] = s2.x; ql[ks][2] = s2.y;
        qh[ks][3] = s3.x; ql[ks][3] = s3.y;
    }

    float pacc[4][4];
    #pragma unroll
    for (int t = 0; t < 4; t++)
        #pragma unroll
        for (int v = 0; v < 4; v++) pacc[t][v] = 0.f;
    float m = -1e30f, l = 0.f;

    for (int ch = 0; ch < NCH_; ch++) {
        const int cur = ch & 1;
        __syncthreads();
        if (ch + 1 < NCH_) { prefetch(ch + 1, 1 - cur); CP_WAIT(1); }
        else               { CP_WAIT(0); }
        __syncthreads();

        const uint32_t (*Khc)[36] = Kh + cur*BKV_;
        const uint32_t (*Klc)[36] = Kl + cur*BKV_;
        const float    (*Vc)[72]  = Vs + cur*BKV_;

        // ---- S = Q @ K^T  (bf16x2: 3 mmas per (ks,nt)) ----
        float sacc[2][4];
        #pragma unroll
        for (int nt = 0; nt < 2; nt++)
            #pragma unroll
            for (int v = 0; v < 4; v++) sacc[nt][v] = 0.f;
        #pragma unroll
        for (int ks = 0; ks < 4; ks++) {
            #pragma unroll
            for (int nt = 0; nt < 2; nt++) {
                const int jn = nh*16 + nt*8 + g;
                uint32_t bh0 = Khc[jn][ks*8 + tig];
                uint32_t bh1 = Khc[jn][ks*8 + tig + 4];
                uint32_t bl0 = Klc[jn][ks*8 + tig];
                uint32_t bl1 = Klc[jn][ks*8 + tig + 4];
                mma_bf16(sacc[nt], qh[ks], bh0, bh1);
                mma_bf16(sacc[nt], qh[ks], bl0, bl1);
                mma_bf16(sacc[nt], ql[ks], bh0, bh1);
            }
        }
        #pragma unroll
        for (int nt = 0; nt < 2; nt++) {
            *(float2*)&Ss[qm + g    ][nh*16 + nt*8 + 2*tig] = make_float2(sacc[nt][0], sacc[nt][1]);
            *(float2*)&Ss[qm + g + 8][nh*16 + nt*8 + 2*tig] = make_float2(sacc[nt][2], sacc[nt][3]);
        }
        __syncthreads();

        // ---- online softmax (fp32, quad per row) ----
        float sv[8];
        #pragma unroll
        for (int w = 0; w < 8; w++) sv[w] = Ss[rr][qd*8 + w];
        float cm = sv[0];
        #pragma unroll
        for (int w = 1; w < 8; w++) cm = fmaxf(cm, sv[w]);
        cm = fmaxf(cm, __shfl_xor_sync(0xffffffffu, cm, 1));
        cm = fmaxf(cm, __shfl_xor_sync(0xffffffffu, cm, 2));
        float mn   = fmaxf(m, cm);
        float corr = __expf(m - mn);
        float ps   = 0.f;
        #pragma unroll
        for (int w = 0; w < 8; w++) {
            float p = __expf(sv[w] - mn);
            ps += p;
            Ss[rr][qd*8 + w] = p;
        }
        ps += __shfl_xor_sync(0xffffffffu, ps, 1);
        ps += __shfl_xor_sync(0xffffffffu, ps, 2);
        l = l * corr + ps;
        m = mn;
        if (qd == 0) rowscale[rr] = corr;
        __syncthreads();

        // ---- O = O*corr + P @ V  (3xTF32, unchanged proven path) ----
        const float s_g  = rowscale[qm + g];
        const float s_g8 = rowscale[qm + g + 8];
        #pragma unroll
        for (int nt = 0; nt < 4; nt++) {
            pacc[nt][0] *= s_g;  pacc[nt][1] *= s_g;
            pacc[nt][2] *= s_g8; pacc[nt][3] *= s_g8;
        }
        #pragma unroll
        for (int ks = 0; ks < 4; ks++) {
            float p0 = Ss[qm + g    ][ks*8 + tig    ];
            float p1 = Ss[qm + g + 8][ks*8 + tig    ];
            float p2 = Ss[qm + g    ][ks*8 + tig + 4];
            float p3 = Ss[qm + g + 8][ks*8 + tig + 4];
            uint32_t pb[4] = { __float_as_uint(p0), __float_as_uint(p1),
                               __float_as_uint(p2), __float_as_uint(p3) };
            uint32_t psm[4] = { tf32_small(p0), tf32_small(p1),
                                tf32_small(p2), tf32_small(p3) };
            #pragma unroll
            for (int nt = 0; nt < 4; nt++) {
                float w0 = Vc[ks*8 + tig    ][nh*32 + nt*8 + g];
                float w1 = Vc[ks*8 + tig + 4][nh*32 + nt*8 + g];
                uint32_t vb[2] = { __float_as_uint(w0), __float_as_uint(w1) };
                uint32_t vsm[2] = { tf32_small(w0), tf32_small(w1) };
                mma_tf32(pacc[nt], pb,  vb);
                mma_tf32(pacc[nt], pb,  vsm);
                mma_tf32(pacc[nt], psm, vb);
            }
        }
    }

    if (qd == 0) rowinv[rr] = 1.f / l;
    __syncthreads();

    const float i_g  = rowinv[qm + g];
    const float i_g8 = rowinv[qm + g + 8];
    const size_t orow0 = (size_t)(b*T_ + qt*BQ_ + qm + g) * C_ + hoff;
    #pragma unroll
    for (int nt = 0; nt < 4; nt++) {
        const int col = nh*32 + nt*8 + 2*tig;
        *(float2*)&g_AO[orow0 + col]          = make_float2(pacc[nt][0]*i_g,  pacc[nt][1]*i_g);
        *(float2*)&g_AO[orow0 + 8*C_ + col]   = make_float2(pacc[nt][2]*i_g8, pacc[nt][3]*i_g8);
    }
}

// ---------------------------------------------------------------------------
extern "C" void kernel_launch(void* const* d_in, const int* in_sizes, int n_in,
                              void* d_out, int out_size) {
    const float* hs  = (const float*)d_in[0];
    const float* Wq  = (const float*)d_in[1];
    const float* Wk  = (const float*)d_in[2];
    const float* Wv  = (const float*)d_in[3];
    const float* Wo  = (const float*)d_in[4];
    const float* bo  = (const float*)d_in[5];
    const void*  idx = d_in[6];
    float* out = (float*)d_out;

    float *Qp, *Vp, *Ap;
    uint32_t *Khp, *Klp;
    cudaGetSymbolAddress((void**)&Qp,  g_Q);
    cudaGetSymbolAddress((void**)&Khp, g_Khi);
    cudaGetSymbolAddress((void**)&Klp, g_Klo);
    cudaGetSymbolAddress((void**)&Vp,  g_V);
    cudaGetSymbolAddress((void**)&Ap,  g_AO);

    cudaFuncSetAttribute(attn_kernel,
                         cudaFuncAttributeMaxDynamicSharedMemorySize,
                         ATTN_SMEM_BYTES);

    build_kv_kernel<<<B_, 256>>>(idx);

    dim3 gq(C_/128, (B_*T_)/128, 3);    // (10, 45, 3)
    gemm_qkv_kernel<<<gq, 256>>>(hs, Wq, Wk, Wv, Qp, Vp, Khp, Klp);

    dim3 ga(T_/BQ_, H_, B_);            // (9, 20, 10)
    attn_kernel<<<ga, 256, ATTN_SMEM_BYTES>>>();

    dim3 gg(C_/128, (B_*T_)/128);       // (10, 45)
    gemm_o_kernel<<<gg, 256>>>(Ap, Wo, bo, out);
}

// round 17
// speedup vs baseline: 1.3134x; 1.0875x over previous
#include <cuda_runtime.h>
#include <cstdint>

// Problem constants
#define B_    10
#define T_    576
#define C_    1280
#define H_    20
#define HD_   64
#define P_    5
#define NSEL_ 288
#define TK_   1728
#define BQ_   64
#define BKV_  32
#define NCH_  (TK_/BKV_)   // 54

// Scratch (device globals: allocation APIs are forbidden)
__device__ __align__(256) float    g_Q  [B_*T_*C_];
__device__ __align__(256) uint32_t g_Khi[B_*T_*C_/2];   // bf16 pair-packed (d-pairs)
__device__ __align__(256) uint32_t g_Klo[B_*T_*C_/2];   // residual plane
__device__ __align__(256) float    g_V  [B_*T_*C_];
__device__ __align__(256) float    g_AO [B_*T_*C_];
__device__ int g_kvrows[B_*TK_];

// ---------------------------------------------------------------------------
// MMA / LDSM helpers
// ---------------------------------------------------------------------------
__device__ __forceinline__ void mma_tf32(float* c, const uint32_t* a, const uint32_t* b) {
    asm volatile(
        "mma.sync.aligned.m16n8k8.row.col.f32.tf32.tf32.f32 "
        "{%0,%1,%2,%3}, {%4,%5,%6,%7}, {%8,%9}, {%0,%1,%2,%3};"
        : "+f"(c[0]), "+f"(c[1]), "+f"(c[2]), "+f"(c[3])
        : "r"(a[0]), "r"(a[1]), "r"(a[2]), "r"(a[3]), "r"(b[0]), "r"(b[1]));
}

__device__ __forceinline__ void mma_bf16(float* c, const uint32_t* a, uint32_t b0, uint32_t b1) {
    asm volatile(
        "mma.sync.aligned.m16n8k16.row.col.f32.bf16.bf16.f32 "
        "{%0,%1,%2,%3}, {%4,%5,%6,%7}, {%8,%9}, {%0,%1,%2,%3};"
        : "+f"(c[0]), "+f"(c[1]), "+f"(c[2]), "+f"(c[3])
        : "r"(a[0]), "r"(a[1]), "r"(a[2]), "r"(a[3]), "r"(b0), "r"(b1));
}

__device__ __forceinline__ void ldsm_x4(uint32_t* r, uint32_t addr) {
    asm volatile("ldmatrix.sync.aligned.m8n8.x4.shared.b16 {%0,%1,%2,%3}, [%4];"
        : "=r"(r[0]), "=r"(r[1]), "=r"(r[2]), "=r"(r[3]) : "r"(addr));
}
__device__ __forceinline__ void ldsm_x2(uint32_t* r, uint32_t addr) {
    asm volatile("ldmatrix.sync.aligned.m8n8.x2.shared.b16 {%0,%1}, [%2];"
        : "=r"(r[0]), "=r"(r[1]) : "r"(addr));
}

__device__ __forceinline__ uint32_t tf32_small(float v) {
    uint32_t big = __float_as_uint(v) & 0xFFFFE000u;
    return __float_as_uint(v - __uint_as_float(big));
}

// Split (x0,x1) into packed bf16 hi pair and residual lo pair.
__device__ __forceinline__ uint2 bf16x2_split2(float x0, float x1) {
    uint32_t h, l;
    asm("cvt.rn.bf16x2.f32 %0, %1, %2;" : "=r"(h) : "f"(x1), "f"(x0));
    float h0 = __uint_as_float(h << 16);
    float h1 = __uint_as_float(h & 0xFFFF0000u);
    float r0 = x0 - h0, r1 = x1 - h1;
    asm("cvt.rn.bf16x2.f32 %0, %1, %2;" : "=r"(l) : "f"(r1), "f"(r0));
    return make_uint2(h, l);
}

__device__ __forceinline__ uint32_t smem_u32(const void* p) {
    uint32_t a;
    asm("{ .reg .u64 t; cvta.to.shared.u64 t, %1; cvt.u32.u64 %0, t; }" : "=r"(a) : "l"(p));
    return a;
}

#define CP_ASYNC16(smem, gptr) \
    asm volatile("cp.async.cg.shared.global [%0], [%1], 16;" :: "r"(smem), "l"(gptr))
#define CP_COMMIT()  asm volatile("cp.async.commit_group;" ::: "memory")
#define CP_WAIT(n)   asm volatile("cp.async.wait_group %0;" :: "n"(n) : "memory")

// ---------------------------------------------------------------------------
// Build per-(s,i) KV row index table (int64/int32 runtime detect).
// ---------------------------------------------------------------------------
__global__ void build_kv_kernel(const void* __restrict__ idx_raw) {
    const int*       i32 = (const int*)idx_raw;
    const long long* i64 = (const long long*)idx_raw;
    bool is64 = true;
    #pragma unroll 8
    for (int k = 0; k < 64; k++) {
        if (i32[2*k + 1] != 0) { is64 = false; break; }
    }
    const int b = blockIdx.x;
    const int s = b / P_, i = b % P_;
    for (int m = threadIdx.x; m < TK_; m += blockDim.x) {
        int row;
        if (m < (P_-1)*NSEL_) {
            int prel = m / NSEL_;
            int p    = prel + (prel >= i ? 1 : 0);
            int j    = m - prel * NSEL_;
            int tok  = is64 ? (int)i64[p*NSEL_ + j] : i32[p*NSEL_ + j];
            row = (s*P_ + p) * T_ + tok;
        } else {
            row = (s*P_ + i) * T_ + (m - (P_-1)*NSEL_);
        }
        g_kvrows[b*TK_ + m] = row;
    }
}

// ---------------------------------------------------------------------------
// bf16x2 split-precision GEMM with LDSM fragment loads.
// 128x128 CTA tile, 8 warps x 64x32, BK=32 (2 x K=16 steps per stage).
// Fragments via ldmatrix: A x4 per (mt,plane), B x2 per (nt,plane):
// 16 LDSM vs 48 scalar LDS per K=16 step (R15 profile: L1=72.4%, tensor=38.7%).
// Row stride 20 u32 -> 8-row LDSM groups hit all 32 banks once (conflict-free).
// ---------------------------------------------------------------------------
__device__ __forceinline__ void gemm_tile_body(
    const float* __restrict__ A, const float* __restrict__ Bw,
    const float* __restrict__ bias, float* __restrict__ Y,
    uint32_t* __restrict__ khi, uint32_t* __restrict__ klo, int kmode,
    int N, int K, int m0, int n0)
{
    __shared__ uint32_t Ahi[128][20];
    __shared__ uint32_t Alo[128][20];
    __shared__ uint32_t Bhi[128][20];
    __shared__ uint32_t Blo[128][20];

    const int tid = threadIdx.x, wid = tid >> 5, lane = tid & 31;
    const int g = lane >> 2, tig = lane & 3;
    const int wm = (wid & 1) * 64, wn = (wid >> 1) * 32;
    const int NST = K >> 5;

    const uint32_t ahi_b = smem_u32(&Ahi[0][0]);
    const uint32_t alo_b = smem_u32(&Alo[0][0]);
    const uint32_t bhi_b = smem_u32(&Bhi[0][0]);
    const uint32_t blo_b = smem_u32(&Blo[0][0]);

    // LDSM lane->row/k-half mapping (canonical m8n8 layout)
    const int rowAp = wm + ((lane >> 3) & 1) * 8 + (lane & 7);
    const int khA   = lane >> 4;              // 0/1
    const int rowBp = wn + (lane & 7);
    const int khB   = (lane >> 3) & 1;

    const int r = tid >> 1, half = tid & 1;
    const float* pA = A  + (size_t)(m0 + r) * K + half * 16;
    const float* pB = Bw + (size_t)(n0 + r) * K + half * 16;

    float acc[16][4];
    #pragma unroll
    for (int t = 0; t < 16; t++)
        #pragma unroll
        for (int v = 0; v < 4; v++) acc[t][v] = 0.f;

    float4 ra[4], rb[4];
    #pragma unroll
    for (int j = 0; j < 4; j++) {
        ra[j] = *(const float4*)(pA + j*4);
        rb[j] = *(const float4*)(pB + j*4);
    }

    for (int s = 0; s < NST; s++) {
        #pragma unroll
        for (int j = 0; j < 4; j++) {
            uint2 a0 = bf16x2_split2(ra[j].x, ra[j].y);
            uint2 a1 = bf16x2_split2(ra[j].z, ra[j].w);
            uint2 b0 = bf16x2_split2(rb[j].x, rb[j].y);
            uint2 b1 = bf16x2_split2(rb[j].z, rb[j].w);
            const int pc = half*8 + j*2;
            Ahi[r][pc] = a0.x;   Alo[r][pc] = a0.y;
            Ahi[r][pc+1] = a1.x; Alo[r][pc+1] = a1.y;
            Bhi[r][pc] = b0.x;   Blo[r][pc] = b0.y;
            Bhi[r][pc+1] = b1.x; Blo[r][pc+1] = b1.y;
        }
        __syncthreads();

        if (s + 1 < NST) {
            const float* a2 = pA + (s+1) * 32;
            const float* b2 = pB + (s+1) * 32;
            #pragma unroll
            for (int j = 0; j < 4; j++) {
                ra[j] = *(const float4*)(a2 + j*4);
                rb[j] = *(const float4*)(b2 + j*4);
            }
        }

        #pragma unroll
        for (int kb = 0; kb < 16; kb += 8) {      // 2 x K=16 steps
            uint32_t ah[4][4], al[4][4], bh[4][2], bl[4][2];
            #pragma unroll
            for (int mt = 0; mt < 4; mt++) {
                const uint32_t off = (uint32_t)(((rowAp + mt*16)*20 + kb + khA*4) * 4);
                ldsm_x4(ah[mt], ahi_b + off);
                ldsm_x4(al[mt], alo_b + off);
            }
            #pragma unroll
            for (int nt = 0; nt < 4; nt++) {
                const uint32_t off = (uint32_t)(((rowBp + nt*8)*20 + kb + khB*4) * 4);
                ldsm_x2(bh[nt], bhi_b + off);
                ldsm_x2(bl[nt], blo_b + off);
            }
            #pragma unroll
            for (int mt = 0; mt < 4; mt++)
                #pragma unroll
                for (int nt = 0; nt < 4; nt++) {
                    float* c = acc[mt*4 + nt];
                    mma_bf16(c, ah[mt], bh[nt][0], bh[nt][1]);
                    mma_bf16(c, ah[mt], bl[nt][0], bl[nt][1]);
                    mma_bf16(c, al[mt], bh[nt][0], bh[nt][1]);
                }
        }
        __syncthreads();
    }

    #pragma unroll
    for (int mt = 0; mt < 4; mt++) {
        #pragma unroll
        for (int nt = 0; nt < 4; nt++) {
            const float* c = acc[mt*4 + nt];
            const int row = m0 + wm + mt*16 + g;
            const int col = n0 + wn + nt*8 + 2*tig;
            if (kmode) {
                uint2 h0 = bf16x2_split2(c[0], c[1]);
                uint2 h1 = bf16x2_split2(c[2], c[3]);
                const size_t o0 = (size_t)row       * (N/2) + (col >> 1);
                const size_t o1 = (size_t)(row + 8) * (N/2) + (col >> 1);
                khi[o0] = h0.x; klo[o0] = h0.y;
                khi[o1] = h1.x; klo[o1] = h1.y;
            } else {
                float b0c = 0.f, b1c = 0.f;
                if (bias) { b0c = bias[col]; b1c = bias[col + 1]; }
                float2 v0 = make_float2(c[0] + b0c, c[1] + b1c);
                float2 v1 = make_float2(c[2] + b0c, c[3] + b1c);
                *(float2*)(Y + (size_t)row       * N + col) = v0;
                *(float2*)(Y + (size_t)(row + 8) * N + col) = v1;
            }
        }
    }
}

// Fused Q/K/V projection: z selects weight + destination (K -> bf16 planes).
__global__ __launch_bounds__(256) void gemm_qkv_kernel(
    const float* __restrict__ hs,
    const float* __restrict__ Wq, const float* __restrict__ Wk,
    const float* __restrict__ Wv,
    float* __restrict__ Qp, float* __restrict__ Vp,
    uint32_t* __restrict__ khi, uint32_t* __restrict__ klo)
{
    const int z = blockIdx.z;
    const float* Bw = (z == 0) ? Wq : (z == 1) ? Wk : Wv;
    float*       Y  = (z == 0) ? Qp : Vp;
    gemm_tile_body(hs, Bw, nullptr, Y, khi, klo, (z == 1) ? 1 : 0,
                   C_, C_, blockIdx.y * 128, blockIdx.x * 128);
}

__global__ __launch_bounds__(256) void gemm_o_kernel(
    const float* __restrict__ A, const float* __restrict__ Wo,
    const float* __restrict__ bo, float* __restrict__ Y)
{
    gemm_tile_body(A, Wo, bo, Y, nullptr, nullptr, 0,
                   C_, C_, blockIdx.y * 128, blockIdx.x * 128);
}

// ---------------------------------------------------------------------------
// Flash attention (unchanged from passing R15): S in bf16x2, PV in 3xTF32.
// ---------------------------------------------------------------------------
#define QS_OFF   0
#define KH_OFF   (QS_OFF + BQ_*68)
#define KL_OFF   (KH_OFF + 2*BKV_*36)
#define VS_OFF   (KL_OFF + 2*BKV_*36)
#define SS_OFF   (VS_OFF + 2*BKV_*72)
#define RSC_OFF  (SS_OFF + BQ_*36)
#define RIV_OFF  (RSC_OFF + BQ_)
#define ROWS_OFF (RIV_OFF + BQ_)
#define ATTN_SMEM_WORDS (ROWS_OFF + TK_)
#define ATTN_SMEM_BYTES (ATTN_SMEM_WORDS * 4)   // 70912 B -> 2 CTAs/SM

__global__ __launch_bounds__(256, 2) void attn_kernel() {
    extern __shared__ float smx[];
    float    (*Qs)[68] = (float(*)[68])(smx + QS_OFF);
    uint32_t (*Kh)[36] = (uint32_t(*)[36])(smx + KH_OFF);
    uint32_t (*Kl)[36] = (uint32_t(*)[36])(smx + KL_OFF);
    float    (*Vs)[72] = (float(*)[72])(smx + VS_OFF);
    float    (*Ss)[36] = (float(*)[36])(smx + SS_OFF);
    float* rowscale = smx + RSC_OFF;
    float* rowinv   = smx + RIV_OFF;
    int*   rows_s   = (int*)(smx + ROWS_OFF);

    const uint32_t kh_base = smem_u32(&Kh[0][0]);
    const uint32_t kl_base = smem_u32(&Kl[0][0]);
    const uint32_t vs_base = smem_u32(&Vs[0][0]);

    const int qt = blockIdx.x, h = blockIdx.y, b = blockIdx.z;
    const int tid = threadIdx.x, wid = tid >> 5, lane = tid & 31;
    const int g = lane >> 2, tig = lane & 3;
    const int mt = wid & 3, nh = wid >> 2;
    const int qm = mt * 16;
    const int rr = tid >> 2, qd = tid & 3;
    const int hoff = h * HD_;

    for (int m = tid; m < TK_; m += 256) rows_s[m] = g_kvrows[b*TK_ + m];
    for (int idx = tid; idx < BQ_*HD_; idx += 256) {
        int r = idx >> 6, d = idx & 63;
        Qs[r][d] = g_Q[(size_t)(b*T_ + qt*BQ_ + r) * C_ + hoff + d] * 0.125f;
    }
    __syncthreads();

    const int pj = tid >> 3, seg = tid & 7;
    auto prefetch = [&](int ch, int buf) {
        int src = rows_s[ch*BKV_ + pj];
        const uint32_t* gkh = g_Khi + (size_t)src * (C_/2) + (hoff >> 1) + seg*4;
        const uint32_t* gkl = g_Klo + (size_t)src * (C_/2) + (hoff >> 1) + seg*4;
        const float*    gv  = g_V   + (size_t)src * C_ + hoff + seg*8;
        uint32_t skh = kh_base + (uint32_t)(((buf*BKV_ + pj)*36 + seg*4) * 4);
        uint32_t skl = kl_base + (uint32_t)(((buf*BKV_ + pj)*36 + seg*4) * 4);
        uint32_t sv  = vs_base + (uint32_t)(((buf*BKV_ + pj)*72 + seg*8) * 4);
        CP_ASYNC16(skh, gkh);
        CP_ASYNC16(skl, gkl);
        CP_ASYNC16(sv, gv);
        CP_ASYNC16(sv + 16, gv + 4);
        CP_COMMIT();
    };

    prefetch(0, 0);

    uint32_t qh[4][4], ql[4][4];
    #pragma unroll
    for (int ks = 0; ks < 4; ks++) {
        const int d0 = ks*16 + 2*tig;
        float2 x0 = *(float2*)&Qs[qm + g    ][d0];
        float2 x1 = *(float2*)&Qs[qm + g + 8][d0];
        float2 x2 = *(float2*)&Qs[qm + g    ][d0 + 8];
        float2 x3 = *(float2*)&Qs[qm + g + 8][d0 + 8];
        uint2 s0 = bf16x2_split2(x0.x, x0.y);
        uint2 s1 = bf16x2_split2(x1.x, x1.y);
        uint2 s2 = bf16x2_split2(x2.x, x2.y);
        uint2 s3 = bf16x2_split2(x3.x, x3.y);
        qh[ks][0] = s0.x; ql[ks][0] = s0.y;
        qh[ks][1] = s1.x; ql[ks][1] = s1.y;
        qh[ks][2] = s2.x; ql[ks][2] = s2.y;
        qh[ks][3] = s3.x; ql[ks][3] = s3.y;
    }

    float pacc[4][4];
    #pragma unroll
    for (int t = 0; t < 4; t++)
        #pragma unroll
        for (int v = 0; v < 4; v++) pacc[t][v] = 0.f;
    float m = -1e30f, l = 0.f;

    for (int ch = 0; ch < NCH_; ch++) {
        const int cur = ch & 1;
        __syncthreads();
        if (ch + 1 < NCH_) { prefetch(ch + 1, 1 - cur); CP_WAIT(1); }
        else               { CP_WAIT(0); }
        __syncthreads();

        const uint32_t (*Khc)[36] = Kh + cur*BKV_;
        const uint32_t (*Klc)[36] = Kl + cur*BKV_;
        const float    (*Vc)[72]  = Vs + cur*BKV_;

        float sacc[2][4];
        #pragma unroll
        for (int nt = 0; nt < 2; nt++)
            #pragma unroll
            for (int v = 0; v < 4; v++) sacc[nt][v] = 0.f;
        #pragma unroll
        for (int ks = 0; ks < 4; ks++) {
            #pragma unroll
            for (int nt = 0; nt < 2; nt++) {
                const int jn = nh*16 + nt*8 + g;
                uint32_t bh0 = Khc[jn][ks*8 + tig];
                uint32_t bh1 = Khc[jn][ks*8 + tig + 4];
                uint32_t bl0 = Klc[jn][ks*8 + tig];
                uint32_t bl1 = Klc[jn][ks*8 + tig + 4];
                mma_bf16(sacc[nt], qh[ks], bh0, bh1);
                mma_bf16(sacc[nt], qh[ks], bl0, bl1);
                mma_bf16(sacc[nt], ql[ks], bh0, bh1);
            }
        }
        #pragma unroll
        for (int nt = 0; nt < 2; nt++) {
            *(float2*)&Ss[qm + g    ][nh*16 + nt*8 + 2*tig] = make_float2(sacc[nt][0], sacc[nt][1]);
            *(float2*)&Ss[qm + g + 8][nh*16 + nt*8 + 2*tig] = make_float2(sacc[nt][2], sacc[nt][3]);
        }
        __syncthreads();

        float sv[8];
        #pragma unroll
        for (int w = 0; w < 8; w++) sv[w] = Ss[rr][qd*8 + w];
        float cm = sv[0];
        #pragma unroll
        for (int w = 1; w < 8; w++) cm = fmaxf(cm, sv[w]);
        cm = fmaxf(cm, __shfl_xor_sync(0xffffffffu, cm, 1));
        cm = fmaxf(cm, __shfl_xor_sync(0xffffffffu, cm, 2));
        float mn   = fmaxf(m, cm);
        float corr = __expf(m - mn);
        float ps   = 0.f;
        #pragma unroll
        for (int w = 0; w < 8; w++) {
            float p = __expf(sv[w] - mn);
            ps += p;
            Ss[rr][qd*8 + w] = p;
        }
        ps += __shfl_xor_sync(0xffffffffu, ps, 1);
        ps += __shfl_xor_sync(0xffffffffu, ps, 2);
        l = l * corr + ps;
        m = mn;
        if (qd == 0) rowscale[rr] = corr;
        __syncthreads();

        const float s_g  = rowscale[qm + g];
        const float s_g8 = rowscale[qm + g + 8];
        #pragma unroll
        for (int nt = 0; nt < 4; nt++) {
            pacc[nt][0] *= s_g;  pacc[nt][1] *= s_g;
            pacc[nt][2] *= s_g8; pacc[nt][3] *= s_g8;
        }
        #pragma unroll
        for (int ks = 0; ks < 4; ks++) {
            float p0 = Ss[qm + g    ][ks*8 + tig    ];
            float p1 = Ss[qm + g + 8][ks*8 + tig    ];
            float p2 = Ss[qm + g    ][ks*8 + tig + 4];
            float p3 = Ss[qm + g + 8][ks*8 + tig + 4];
            uint32_t pb[4] = { __float_as_uint(p0), __float_as_uint(p1),
                               __float_as_uint(p2), __float_as_uint(p3) };
            uint32_t psm[4] = { tf32_small(p0), tf32_small(p1),
                                tf32_small(p2), tf32_small(p3) };
            #pragma unroll
            for (int nt = 0; nt < 4; nt++) {
                float w0 = Vc[ks*8 + tig    ][nh*32 + nt*8 + g];
                float w1 = Vc[ks*8 + tig + 4][nh*32 + nt*8 + g];
                uint32_t vb[2] = { __float_as_uint(w0), __float_as_uint(w1) };
                uint32_t vsm[2] = { tf32_small(w0), tf32_small(w1) };
                mma_tf32(pacc[nt], pb,  vb);
                mma_tf32(pacc[nt], pb,  vsm);
                mma_tf32(pacc[nt], psm, vb);
            }
        }
    }

    if (qd == 0) rowinv[rr] = 1.f / l;
    __syncthreads();

    const float i_g  = rowinv[qm + g];
    const float i_g8 = rowinv[qm + g + 8];
    const size_t orow0 = (size_t)(b*T_ + qt*BQ_ + qm + g) * C_ + hoff;
    #pragma unroll
    for (int nt = 0; nt < 4; nt++) {
        const int col = nh*32 + nt*8 + 2*tig;
        *(float2*)&g_AO[orow0 + col]          = make_float2(pacc[nt][0]*i_g,  pacc[nt][1]*i_g);
        *(float2*)&g_AO[orow0 + 8*C_ + col]   = make_float2(pacc[nt][2]*i_g8, pacc[nt][3]*i_g8);
    }
}

// ---------------------------------------------------------------------------
extern "C" void kernel_launch(void* const* d_in, const int* in_sizes, int n_in,
                              void* d_out, int out_size) {
    const float* hs  = (const float*)d_in[0];
    const float* Wq  = (const float*)d_in[1];
    const float* Wk  = (const float*)d_in[2];
    const float* Wv  = (const float*)d_in[3];
    const float* Wo  = (const float*)d_in[4];
    const float* bo  = (const float*)d_in[5];
    const void*  idx = d_in[6];
    float* out = (float*)d_out;

    float *Qp, *Vp, *Ap;
    uint32_t *Khp, *Klp;
    cudaGetSymbolAddress((void**)&Qp,  g_Q);
    cudaGetSymbolAddress((void**)&Khp, g_Khi);
    cudaGetSymbolAddress((void**)&Klp, g_Klo);
    cudaGetSymbolAddress((void**)&Vp,  g_V);
    cudaGetSymbolAddress((void**)&Ap,  g_AO);

    cudaFuncSetAttribute(attn_kernel,
                         cudaFuncAttributeMaxDynamicSharedMemorySize,
                         ATTN_SMEM_BYTES);

    build_kv_kernel<<<B_, 256>>>(idx);

    dim3 gq(C_/128, (B_*T_)/128, 3);    // (10, 45, 3)
    gemm_qkv_kernel<<<gq, 256>>>(hs, Wq, Wk, Wv, Qp, Vp, Khp, Klp);

    dim3 ga(T_/BQ_, H_, B_);            // (9, 20, 10)
    attn_kernel<<<ga, 256, ATTN_SMEM_BYTES>>>();

    dim3 gg(C_/128, (B_*T_)/128);       // (10, 45)
    gemm_o_kernel<<<gg, 256>>>(Ap, Wo, bo, out);
}